// round 1
// baseline (speedup 1.0000x reference)
#include <cuda_runtime.h>
#include <math.h>

#define NSIDE 128
#define SLICES 1024
#define PLANE 16777216ull   // 1024 * 128 * 128

// Scratch: Y1t/Y2t stored transposed [slice][q][m] as float2 (complex)
__device__ float2 g_Y1[SLICES * NSIDE * NSIDE];
__device__ float2 g_Y2[SLICES * NSIDE * NSIDE];

extern __shared__ float sm[];

// Stockham radix-2 128-pt FFT, one warp, 2 butterflies/thread, ping-pong A<->B.
// Input in (Ar,Ai) natural order; output lands in (Br,Bi) natural order.
// Unscaled (inverse pass does NOT divide by N; scaling folded into spectral mult).
template <bool INV>
__device__ __forceinline__ void fft128(float* Ar, float* Ai, float* Br, float* Bi,
                                       const float* twr, const float* twi, int t)
{
    float *ar = Ar, *ai = Ai, *br = Br, *bi = Bi;
#pragma unroll
    for (int stage = 0; stage < 7; ++stage) {
        const int m = 1 << stage;
#pragma unroll
        for (int h = 0; h < 2; ++h) {
            int b  = t + 32 * h;          // butterfly index 0..63
            int rr = b & ~(m - 1);        // twiddle index (128th roots)
            int o0 = b + rr;
            float wr = twr[rr];
            float wi = INV ? -twi[rr] : twi[rr];
            float x0r = ar[b],      x0i = ai[b];
            float x1r = ar[b + 64], x1i = ai[b + 64];
            br[o0] = x0r + x1r;
            bi[o0] = x0i + x1i;
            float dr = x0r - x1r, di = x0i - x1i;
            br[o0 + m] = dr * wr - di * wi;
            bi[o0 + m] = dr * wi + di * wr;
        }
        float* tp;
        tp = ar; ar = br; br = tp;
        tp = ai; ai = bi; bi = tp;
        __syncwarp();
    }
}

// ---------------------------------------------------------------------------
// P1: per slice — row FFTs into smem spectrum, then per column:
// forward FFT over m, multiply by W/N^2 and W^2/N^2, inverse FFT over m,
// write transposed Y1t/Y2t[s][q][m] to global scratch.
// smem: Fre/Fim 128x129 (pad->conflict-free col reads) + 16 warp buffers + tw
// ---------------------------------------------------------------------------
__global__ void __launch_bounds__(512) p1_kernel(const float* __restrict__ x)
{
    const int s   = blockIdx.x;
    const int tid = threadIdx.x;
    const int u   = tid >> 5;
    const int t   = tid & 31;

    float* Fre = sm;                    // 128*129
    float* Fim = Fre + 128 * 129;       // 128*129
    float* ub  = Fim + 128 * 129;       // 16 * 512
    float* twr = ub + 16 * 512;         // 64
    float* twi = twr + 64;              // 64

    float* Ar = ub + u * 512;
    float* Ai = Ar + 128;
    float* Br = Ai + 128;
    float* Bi = Br + 128;

    if (tid < 64) {
        float ang = -2.0f * 3.14159265358979323846f * (float)tid / 128.0f;
        float sv, cv;
        sincosf(ang, &sv, &cv);
        twr[tid] = cv;
        twi[tid] = sv;
    }
    __syncthreads();

    const float* xs = x + (size_t)s * (NSIDE * NSIDE);

    // ---- forward row FFTs (real input) ----
#pragma unroll 1
    for (int it = 0; it < 8; ++it) {
        int m = it * 16 + u;
        const float* row = xs + m * NSIDE;
#pragma unroll
        for (int r = 0; r < 4; ++r) {
            int n = t + 32 * r;
            Ar[n] = row[n];
            Ai[n] = 0.0f;
        }
        __syncwarp();
        fft128<false>(Ar, Ai, Br, Bi, twr, twi, t);
#pragma unroll
        for (int r = 0; r < 4; ++r) {
            int q = t + 32 * r;
            Fre[m * 129 + q] = Br[q];
            Fim[m * 129 + q] = Bi[q];
        }
        __syncwarp();
    }
    __syncthreads();

    const float sc = 1.0f / 16384.0f;   // 1/N^2 (both ifft normalizations)

    // ---- per column: fwd FFT over m, multiply, 2x inverse, store ----
#pragma unroll 1
    for (int it = 0; it < 8; ++it) {
        int q = it * 16 + u;
        float kq = (q < 64) ? (float)q : (float)(q - 128);

#pragma unroll
        for (int r = 0; r < 4; ++r) {
            int p = t + 32 * r;
            Ar[p] = Fre[p * 129 + q];
            Ai[p] = Fim[p * 129 + q];
        }
        __syncwarp();
        fft128<false>(Ar, Ai, Br, Bi, twr, twi, t);

        float fr[4], fi[4];
#pragma unroll
        for (int r = 0; r < 4; ++r) {
            int p = t + 32 * r;
            fr[r] = Br[p];
            fi[r] = Bi[p];
        }

        // G1 = (i*kp - kq) * F * sc
#pragma unroll
        for (int r = 0; r < 4; ++r) {
            int p = t + 32 * r;
            float kp = (p < 64) ? (float)p : (float)(p - 128);
            float w1r = -kq * sc, w1i = kp * sc;
            Ar[p] = w1r * fr[r] - w1i * fi[r];
            Ai[p] = w1r * fi[r] + w1i * fr[r];
        }
        __syncwarp();
        fft128<true>(Ar, Ai, Br, Bi, twr, twi, t);
        {
            float2* y1 = g_Y1 + ((size_t)(s * NSIDE + q)) * NSIDE;
#pragma unroll
            for (int r = 0; r < 4; ++r) {
                int mm = t + 32 * r;
                y1[mm] = make_float2(Br[mm], Bi[mm]);
            }
        }

        // G2 = ((kq^2 - kp^2) - i*2*kp*kq) * F * sc
#pragma unroll
        for (int r = 0; r < 4; ++r) {
            int p = t + 32 * r;
            float kp = (p < 64) ? (float)p : (float)(p - 128);
            float w2r = (kq * kq - kp * kp) * sc;
            float w2i = (-2.0f * kp * kq) * sc;
            Ar[p] = w2r * fr[r] - w2i * fi[r];
            Ai[p] = w2r * fi[r] + w2i * fr[r];
        }
        __syncwarp();
        fft128<true>(Ar, Ai, Br, Bi, twr, twi, t);
        {
            float2* y2 = g_Y2 + ((size_t)(s * NSIDE + q)) * NSIDE;
#pragma unroll
            for (int r = 0; r < 4; ++r) {
                int mm = t + 32 * r;
                y2[mm] = make_float2(Br[mm], Bi[mm]);
            }
        }
        __syncwarp();
    }
}

// ---------------------------------------------------------------------------
// P2: per (slice, 32-row tile) — load Y1t/Y2t tiles coalesced, transpose via
// padded smem, inverse row FFTs over q -> dx0/d2x0, fused epilogue, 5 outputs.
// ---------------------------------------------------------------------------
__global__ void __launch_bounds__(512) p2_kernel(float* __restrict__ out,
                                                 const float* __restrict__ df,
                                                 const float* __restrict__ d2f)
{
    const int s    = blockIdx.x;
    const int tile = blockIdx.y;
    const int m0   = tile * 32;
    const int tid  = threadIdx.x;
    const int u    = tid >> 5;
    const int t    = tid & 31;

    float* T1r = sm;            // 128 * 33
    float* T1i = T1r + 4224;
    float* T2r = T1i + 4224;
    float* T2i = T2r + 4224;
    float* ub  = T2i + 4224;    // 16 * 512
    float* twr = ub + 16 * 512; // 64
    float* twi = twr + 64;      // 64

    float* Ar = ub + u * 512;
    float* Ai = Ar + 128;
    float* Br = Ai + 128;
    float* Bi = Br + 128;

    if (tid < 64) {
        float ang = -2.0f * 3.14159265358979323846f * (float)tid / 128.0f;
        float sv, cv;
        sincosf(ang, &sv, &cv);
        twr[tid] = cv;
        twi[tid] = sv;
    }

    // coalesced tile load: [q][mm], mm fastest
    const float2* y1 = g_Y1 + (size_t)s * (NSIDE * NSIDE);
    const float2* y2 = g_Y2 + (size_t)s * (NSIDE * NSIDE);
#pragma unroll
    for (int i = 0; i < 8; ++i) {
        int e  = i * 512 + tid;
        int q  = e >> 5;
        int mm = e & 31;
        float2 v1 = y1[q * NSIDE + m0 + mm];
        T1r[q * 33 + mm] = v1.x;
        T1i[q * 33 + mm] = v1.y;
        float2 v2 = y2[q * NSIDE + m0 + mm];
        T2r[q * 33 + mm] = v2.x;
        T2i[q * 33 + mm] = v2.y;
    }
    __syncthreads();

    // per-channel params
    const int c  = s & 63;
    float df0 = df[2 * c], df1 = df[2 * c + 1];
    float ed  = expf(df0);
    float dfcr = ed * cosf(df1), dfci = ed * sinf(df1);
    float d20 = d2f[2 * c], d21 = d2f[2 * c + 1];
    float inv_nf = 0.5f / (dfcr * dfcr + dfci * dfci);
    float hrr = (d20 * dfcr + d21 * dfci) * inv_nf;   // 0.5 * d2fc/dfc (re)
    float hri = (d21 * dfcr - d20 * dfci) * inv_nf;   // 0.5 * d2fc/dfc (im)

    const float EPS2     = 1e-6f;           // (1e-3)^2
    const float LN_EPS   = -6.9077552790f;  // log(0.001)
    const float TR_MIN   = -2.5902671570f;  // log(0.075)

#pragma unroll 1
    for (int iter = 0; iter < 2; ++iter) {
        int mm = iter * 16 + u;
        int m  = m0 + mm;

        // dx0 row: inverse FFT over q of Y1t[:, m]
#pragma unroll
        for (int r = 0; r < 4; ++r) {
            int qq = t + 32 * r;
            Ar[qq] = T1r[qq * 33 + mm];
            Ai[qq] = T1i[qq * 33 + mm];
        }
        __syncwarp();
        fft128<true>(Ar, Ai, Br, Bi, twr, twi, t);
        float dxr[4], dxi[4];
#pragma unroll
        for (int r = 0; r < 4; ++r) {
            int n = t + 32 * r;
            dxr[r] = Br[n];
            dxi[r] = Bi[n];
        }

        // d2x0 row
#pragma unroll
        for (int r = 0; r < 4; ++r) {
            int qq = t + 32 * r;
            Ar[qq] = T2r[qq * 33 + mm];
            Ai[qq] = T2i[qq * 33 + mm];
        }
        __syncwarp();
        fft128<true>(Ar, Ai, Br, Bi, twr, twi, t);

        size_t base = (size_t)s * 16384 + (size_t)m * 128;
#pragma unroll
        for (int r = 0; r < 4; ++r) {
            int n = t + 32 * r;
            float Dr0 = dxr[r], Di0 = dxi[r];
            float d2r = Br[n],  d2i = Bi[n];

            float h = Dr0 * Dr0 + Di0 * Di0;
            bool valid = (h >= EPS2);
            float Dr = valid ? Dr0 : 1.0f;
            float Di = valid ? Di0 : 0.0f;
            float nD = valid ? h : 1.0f;
            float invnD = 1.0f / nD;

            // a2 = dfc / D = dfc * conj(D) / |D|^2
            float a2r = (dfcr * Dr + dfci * Di) * invnD;
            float a2i = (dfci * Dr - dfcr * Di) * invnD;

            float lnA = 0.0f, Phi = 0.0f;
            if (valid) {
                float la = 0.5f * logf(a2r * a2r + a2i * a2i);
                lnA = fminf(3.0f, fmaxf(-3.0f, la));
                Phi = atan2f(a2i, a2r);
            }

            // an = 0.5*(d2x0*dfc)*conj(D^2)/|D|^4 - 0.5*d2fc/dfc
            float t1r = d2r * dfcr - d2i * dfci;
            float t1i = d2r * dfci + d2i * dfcr;
            float D2r = Dr * Dr - Di * Di;
            float D2i = 2.0f * Dr * Di;
            float invn2 = invnD * invnD;
            float anr = 0.5f * (t1r * D2r + t1i * D2i) * invn2 - hrr;
            float ani = 0.5f * (t1i * D2r - t1r * D2i) * invn2 - hri;

            float na = anr * anr + ani * ani;
            bool tm = valid && (na >= EPS2);
            float lnT = LN_EPS, Psi = 0.0f;
            if (tm) {
                float lt = 0.5f * logf(na);
                lnT = fminf(3.0f, fmaxf(TR_MIN, lt));
                Psi = atan2f(ani, anr);
            }

            out[base + n]             = h;
            out[PLANE + base + n]     = lnA;
            out[2 * PLANE + base + n] = Phi;
            out[3 * PLANE + base + n] = lnT;
            out[4 * PLANE + base + n] = Psi;
        }
    }
}

extern "C" void kernel_launch(void* const* d_in, const int* in_sizes, int n_in,
                              void* d_out, int out_size)
{
    const float* x   = (const float*)d_in[0];
    const float* df  = (const float*)d_in[1];
    const float* d2f = (const float*)d_in[2];
    float* out = (float*)d_out;

    const int P1_SMEM = (2 * 128 * 129 + 16 * 512 + 128) * 4;  // 165376 B
    const int P2_SMEM = (4 * 4224 + 16 * 512 + 128) * 4;       // 100864 B

    cudaFuncSetAttribute(p1_kernel, cudaFuncAttributeMaxDynamicSharedMemorySize, P1_SMEM);
    cudaFuncSetAttribute(p2_kernel, cudaFuncAttributeMaxDynamicSharedMemorySize, P2_SMEM);

    p1_kernel<<<SLICES, 512, P1_SMEM>>>(x);
    p2_kernel<<<dim3(SLICES, 4), 512, P2_SMEM>>>(out, df, d2f);
}

// round 2
// speedup vs baseline: 1.8288x; 1.8288x over previous
#include <cuda_runtime.h>
#include <math.h>

#define NSIDE 128
#define SLICES 1024
#define PLANE 16777216ull   // 1024 * 128 * 128

// Scratch: Y1/Y2 stored [slice][qs][n-natural] as float2, qs = storage-permuted q
__device__ float2 g_Y1[SLICES * NSIDE * NSIDE];
__device__ float2 g_Y2[SLICES * NSIDE * NSIDE];

// ---------------------------------------------------------------------------
// Register/shuffle 128-pt FFT: 128 = 32 lanes x 4 regs.
// Input layout (P4):  thread t holds x[4t + j], j = reg 0..3
// Output layout (SP): thread b, reg k1 holds X[bitrev5(b) + 32*k1]
// Inverse consumes SP, produces P4, UNSCALED (x128); scaling folded by caller.
// ---------------------------------------------------------------------------
struct Tw {
    float w16r, w16i, w8r, w8i, w4r, w4i, w2r, w2i;  // masked fwd stage twiddles
    float c1, s1, c2, s2, c3, s3;                    // cos/sin(k*theta), theta=2pi*brev(t)/128
};

__device__ __forceinline__ void stage_tw(int t, int h, float& cr, float& ci)
{
    if (t & h) {
        float a = -3.14159265358979323846f * (float)(t & (h - 1)) / (float)h;
        sincosf(a, &ci, &cr);
    } else { cr = 1.0f; ci = 0.0f; }
}

__device__ __forceinline__ void make_tw(Tw& T, int t)
{
    int br = __brev(t) >> 27;
    float th = 6.283185307179586f * (float)br / 128.0f;
    sincosf(th, &T.s1, &T.c1);
    sincosf(2.0f * th, &T.s2, &T.c2);
    sincosf(3.0f * th, &T.s3, &T.c3);
    stage_tw(t, 16, T.w16r, T.w16i);
    stage_tw(t, 8,  T.w8r,  T.w8i);
    stage_tw(t, 4,  T.w4r,  T.w4i);
    stage_tw(t, 2,  T.w2r,  T.w2i);
}

__device__ __forceinline__ void cmulm(float& ar, float& ai, float br, float bi)
{
    float r = ar * br - ai * bi;
    ai = ar * bi + ai * br;
    ar = r;
}

template <int H>
__device__ __forceinline__ void lane_stage_f(float vr[4], float vi[4],
                                             float twr, float twi, int t)
{
    float e = (t & H) ? -1.0f : 1.0f;
#pragma unroll
    for (int r = 0; r < 4; ++r) {
        float pr = __shfl_xor_sync(0xffffffffu, vr[r], H);
        float pi = __shfl_xor_sync(0xffffffffu, vi[r], H);
        float ur = fmaf(e, vr[r], pr);
        float ui = fmaf(e, vi[r], pi);
        vr[r] = ur * twr - ui * twi;
        vi[r] = fmaf(ur, twi, ui * twr);
    }
}

__device__ __forceinline__ void lane_stage_f1(float vr[4], float vi[4], int t)
{
    float e = (t & 1) ? -1.0f : 1.0f;
#pragma unroll
    for (int r = 0; r < 4; ++r) {
        float pr = __shfl_xor_sync(0xffffffffu, vr[r], 1);
        float pi = __shfl_xor_sync(0xffffffffu, vi[r], 1);
        vr[r] = fmaf(e, vr[r], pr);
        vi[r] = fmaf(e, vi[r], pi);
    }
}

template <int H>
__device__ __forceinline__ void lane_stage_i(float vr[4], float vi[4],
                                             float twr, float twi, int t)
{
    float e = (t & H) ? -1.0f : 1.0f;
#pragma unroll
    for (int r = 0; r < 4; ++r) {
        // pre-multiply by conj(masked tw)
        float ar = fmaf(vi[r], twi, vr[r] * twr);
        float ai = vi[r] * twr - vr[r] * twi;
        float pr = __shfl_xor_sync(0xffffffffu, ar, H);
        float pi = __shfl_xor_sync(0xffffffffu, ai, H);
        vr[r] = fmaf(e, ar, pr);
        vi[r] = fmaf(e, ai, pi);
    }
}

__device__ __forceinline__ void lane_stage_i1(float vr[4], float vi[4], int t)
{
    float e = (t & 1) ? -1.0f : 1.0f;
#pragma unroll
    for (int r = 0; r < 4; ++r) {
        float pr = __shfl_xor_sync(0xffffffffu, vr[r], 1);
        float pi = __shfl_xor_sync(0xffffffffu, vi[r], 1);
        vr[r] = fmaf(e, vr[r], pr);
        vi[r] = fmaf(e, vi[r], pi);
    }
}

__device__ __forceinline__ void fft_fwd(float vr[4], float vi[4], const Tw& T, int t)
{
    lane_stage_f<16>(vr, vi, T.w16r, T.w16i, t);
    lane_stage_f<8>(vr, vi, T.w8r, T.w8i, t);
    lane_stage_f<4>(vr, vi, T.w4r, T.w4i, t);
    lane_stage_f<2>(vr, vi, T.w2r, T.w2i, t);
    lane_stage_f1(vr, vi, t);
    // T twiddle: reg n1 *= e^{-i n1 theta}
    cmulm(vr[1], vi[1], T.c1, -T.s1);
    cmulm(vr[2], vi[2], T.c2, -T.s2);
    cmulm(vr[3], vi[3], T.c3, -T.s3);
    // 4-pt DFT over regs (DIF)
    float s02r = vr[0] + vr[2], s02i = vi[0] + vi[2];
    float d02r = vr[0] - vr[2], d02i = vi[0] - vi[2];
    float s13r = vr[1] + vr[3], s13i = vi[1] + vi[3];
    float d13r = vr[1] - vr[3], d13i = vi[1] - vi[3];
    vr[0] = s02r + s13r; vi[0] = s02i + s13i;
    vr[2] = s02r - s13r; vi[2] = s02i - s13i;
    vr[1] = d02r + d13i; vi[1] = d02i - d13r;
    vr[3] = d02r - d13i; vi[3] = d02i + d13r;
}

__device__ __forceinline__ void fft_inv(float vr[4], float vi[4], const Tw& T, int t)
{
    // 4-pt inverse DFT over regs
    float s02r = vr[0] + vr[2], s02i = vi[0] + vi[2];
    float d02r = vr[0] - vr[2], d02i = vi[0] - vi[2];
    float s13r = vr[1] + vr[3], s13i = vi[1] + vi[3];
    float d13r = vr[1] - vr[3], d13i = vi[1] - vi[3];
    vr[0] = s02r + s13r; vi[0] = s02i + s13i;
    vr[2] = s02r - s13r; vi[2] = s02i - s13i;
    vr[1] = d02r - d13i; vi[1] = d02i + d13r;
    vr[3] = d02r + d13i; vi[3] = d02i - d13r;
    // conj T twiddle
    cmulm(vr[1], vi[1], T.c1, T.s1);
    cmulm(vr[2], vi[2], T.c2, T.s2);
    cmulm(vr[3], vi[3], T.c3, T.s3);
    // lane stages in reverse order
    lane_stage_i1(vr, vi, t);
    lane_stage_i<2>(vr, vi, T.w2r, T.w2i, t);
    lane_stage_i<4>(vr, vi, T.w4r, T.w4i, t);
    lane_stage_i<8>(vr, vi, T.w8r, T.w8i, t);
    lane_stage_i<16>(vr, vi, T.w16r, T.w16i, t);
}

// ---------------------------------------------------------------------------
// P1: per slice. Row FFTs -> swizzled smem spectrum -> per storage-column:
// fwd FFT over m, W1/W2 multiply (in bitrev spectral coords), 2x inverse,
// store Y1/Y2[s][qs][n] coalesced.
// smem: Fre/Fim 128x128 floats, XOR swizzle col ^ ((row>>2)&31). 131072 B.
// ---------------------------------------------------------------------------
__global__ void __launch_bounds__(512) p1_kernel(const float* __restrict__ x)
{
    extern __shared__ float sm[];
    float* Fre = sm;
    float* Fim = sm + 16384;

    const int s   = blockIdx.x;
    const int tid = threadIdx.x;
    const int u   = tid >> 5;
    const int t   = tid & 31;

    Tw T;
    make_tw(T, t);

    const float4* xs = (const float4*)(x + (size_t)s * (NSIDE * NSIDE));

    // ---- forward row FFTs ----
#pragma unroll 1
    for (int it = 0; it < 8; ++it) {
        int m = it * 16 + u;
        float4 v = xs[m * 32 + t];
        float vr[4] = { v.x, v.y, v.z, v.w };
        float vi[4] = { 0.0f, 0.0f, 0.0f, 0.0f };
        fft_fwd(vr, vi, T, t);
        int C = (m >> 2) & 31;
        int rowb = m << 7;
#pragma unroll
        for (int k1 = 0; k1 < 4; ++k1) {
            int sc = (t + (k1 << 5)) ^ C;
            Fre[rowb + sc] = vr[k1];
            Fim[rowb + sc] = vi[k1];
        }
    }
    __syncthreads();

    const float scale = 1.0f / 16384.0f;
    const int brv = __brev(t) >> 27;

    // ---- per storage column ----
#pragma unroll 1
    for (int it = 0; it < 8; ++it) {
        int qs = it * 16 + u;
        int q_idx = (__brev(qs & 31) >> 27) + (qs & 96);
        float kq = (q_idx < 64) ? (float)q_idx : (float)(q_idx - 128);

        float vr[4], vi[4];
#pragma unroll
        for (int j = 0; j < 4; ++j) {
            int p = 4 * t + j;
            int sc = qs ^ t;              // qs ^ ((p>>2)&31)
            vr[j] = Fre[(p << 7) + sc];
            vi[j] = Fim[(p << 7) + sc];
        }
        fft_fwd(vr, vi, T, t);

        float fr[4], fi[4];
#pragma unroll
        for (int k1 = 0; k1 < 4; ++k1) { fr[k1] = vr[k1]; fi[k1] = vi[k1]; }

        // G1 = (i*kp - kq) * F * scale
#pragma unroll
        for (int k1 = 0; k1 < 4; ++k1) {
            int p_idx = brv + (k1 << 5);
            float kp = (p_idx < 64) ? (float)p_idx : (float)(p_idx - 128);
            float w1r = -kq * scale, w1i = kp * scale;
            vr[k1] = fr[k1] * w1r - fi[k1] * w1i;
            vi[k1] = fr[k1] * w1i + fi[k1] * w1r;
        }
        fft_inv(vr, vi, T, t);
        {
            float4* y = (float4*)(g_Y1 + ((size_t)s * NSIDE + qs) * NSIDE + 4 * t);
            y[0] = make_float4(vr[0], vi[0], vr[1], vi[1]);
            y[1] = make_float4(vr[2], vi[2], vr[3], vi[3]);
        }

        // G2 = ((kq^2 - kp^2) - i*2*kp*kq) * F * scale
#pragma unroll
        for (int k1 = 0; k1 < 4; ++k1) {
            int p_idx = brv + (k1 << 5);
            float kp = (p_idx < 64) ? (float)p_idx : (float)(p_idx - 128);
            float w2r = (kq * kq - kp * kp) * scale;
            float w2i = -2.0f * kp * kq * scale;
            vr[k1] = fr[k1] * w2r - fi[k1] * w2i;
            vi[k1] = fr[k1] * w2i + fi[k1] * w2r;
        }
        fft_inv(vr, vi, T, t);
        {
            float4* y = (float4*)(g_Y2 + ((size_t)s * NSIDE + qs) * NSIDE + 4 * t);
            y[0] = make_float4(vr[0], vi[0], vr[1], vi[1]);
            y[1] = make_float4(vr[2], vi[2], vr[3], vi[3]);
        }
    }
}

// ---------------------------------------------------------------------------
// P2: per (slice, 32-row tile). Load Y1/Y2 tiles coalesced, transpose via
// stride-33 smem, inverse row FFT over q (register/shuffle), fused epilogue.
// smem: 4 * 128*33 floats = 67584 B -> 2 CTAs/SM.
// ---------------------------------------------------------------------------
__global__ void __launch_bounds__(512, 2) p2_kernel(float* __restrict__ out,
                                                    const float* __restrict__ df,
                                                    const float* __restrict__ d2f)
{
    extern __shared__ float sm[];
    float* T1r = sm;
    float* T1i = T1r + 4224;
    float* T2r = T1i + 4224;
    float* T2i = T2r + 4224;

    const int s    = blockIdx.x;
    const int m0   = blockIdx.y * 32;
    const int tid  = threadIdx.x;
    const int u    = tid >> 5;
    const int t    = tid & 31;

    Tw T;
    make_tw(T, t);

    const float2* y1 = g_Y1 + (size_t)s * (NSIDE * NSIDE);
    const float2* y2 = g_Y2 + (size_t)s * (NSIDE * NSIDE);
#pragma unroll
    for (int i = 0; i < 8; ++i) {
        int e  = i * 512 + tid;
        int q  = e >> 5;
        int mm = e & 31;
        float2 v1 = y1[q * NSIDE + m0 + mm];
        T1r[q * 33 + mm] = v1.x;
        T1i[q * 33 + mm] = v1.y;
        float2 v2 = y2[q * NSIDE + m0 + mm];
        T2r[q * 33 + mm] = v2.x;
        T2i[q * 33 + mm] = v2.y;
    }
    __syncthreads();

    // per-channel params
    const int c = s & 63;
    float df0 = df[2 * c], df1 = df[2 * c + 1];
    float ed  = expf(df0);
    float dfcr = ed * cosf(df1), dfci = ed * sinf(df1);
    float d20 = d2f[2 * c], d21 = d2f[2 * c + 1];
    float inv_nf = 0.5f / (dfcr * dfcr + dfci * dfci);
    float hrr = (d20 * dfcr + d21 * dfci) * inv_nf;
    float hri = (d21 * dfcr - d20 * dfci) * inv_nf;

    const float EPS2   = 1e-6f;
    const float LN_EPS = -6.9077552790f;
    const float TR_MIN = -2.5902671570f;

#pragma unroll 1
    for (int iter = 0; iter < 2; ++iter) {
        int mm = iter * 16 + u;
        int m  = m0 + mm;

        float dxr[4], dxi[4];
        {
            float vr[4], vi[4];
#pragma unroll
            for (int k1 = 0; k1 < 4; ++k1) {
                int qs = t + (k1 << 5);
                vr[k1] = T1r[qs * 33 + mm];
                vi[k1] = T1i[qs * 33 + mm];
            }
            fft_inv(vr, vi, T, t);
#pragma unroll
            for (int j = 0; j < 4; ++j) { dxr[j] = vr[j]; dxi[j] = vi[j]; }
        }

        float d2r_[4], d2i_[4];
        {
            float vr[4], vi[4];
#pragma unroll
            for (int k1 = 0; k1 < 4; ++k1) {
                int qs = t + (k1 << 5);
                vr[k1] = T2r[qs * 33 + mm];
                vi[k1] = T2i[qs * 33 + mm];
            }
            fft_inv(vr, vi, T, t);
#pragma unroll
            for (int j = 0; j < 4; ++j) { d2r_[j] = vr[j]; d2i_[j] = vi[j]; }
        }

        float oh[4], oa[4], op[4], ot[4], os[4];
#pragma unroll
        for (int j = 0; j < 4; ++j) {
            float Dr0 = dxr[j], Di0 = dxi[j];
            float d2r = d2r_[j], d2i = d2i_[j];

            float h = Dr0 * Dr0 + Di0 * Di0;
            bool valid = (h >= EPS2);
            float Dr = valid ? Dr0 : 1.0f;
            float Di = valid ? Di0 : 0.0f;
            float nD = valid ? h : 1.0f;
            float invnD = 1.0f / nD;

            float a2r = (dfcr * Dr + dfci * Di) * invnD;
            float a2i = (dfci * Dr - dfcr * Di) * invnD;

            float lnA = 0.0f, Phi = 0.0f;
            if (valid) {
                float la = 0.5f * logf(a2r * a2r + a2i * a2i);
                lnA = fminf(3.0f, fmaxf(-3.0f, la));
                Phi = atan2f(a2i, a2r);
            }

            float t1r = d2r * dfcr - d2i * dfci;
            float t1i = d2r * dfci + d2i * dfcr;
            float D2r = Dr * Dr - Di * Di;
            float D2i = 2.0f * Dr * Di;
            float invn2 = invnD * invnD;
            float anr = 0.5f * (t1r * D2r + t1i * D2i) * invn2 - hrr;
            float ani = 0.5f * (t1i * D2r - t1r * D2i) * invn2 - hri;

            float na = anr * anr + ani * ani;
            bool tm = valid && (na >= EPS2);
            float lnT = LN_EPS, Psi = 0.0f;
            if (tm) {
                float lt = 0.5f * logf(na);
                lnT = fminf(3.0f, fmaxf(TR_MIN, lt));
                Psi = atan2f(ani, anr);
            }

            oh[j] = h; oa[j] = lnA; op[j] = Phi; ot[j] = lnT; os[j] = Psi;
        }

        size_t base = (size_t)s * 16384 + (size_t)m * 128;
        ((float4*)(out + base))[t]             = *(float4*)oh;
        ((float4*)(out + PLANE + base))[t]     = *(float4*)oa;
        ((float4*)(out + 2 * PLANE + base))[t] = *(float4*)op;
        ((float4*)(out + 3 * PLANE + base))[t] = *(float4*)ot;
        ((float4*)(out + 4 * PLANE + base))[t] = *(float4*)os;
    }
}

extern "C" void kernel_launch(void* const* d_in, const int* in_sizes, int n_in,
                              void* d_out, int out_size)
{
    const float* x   = (const float*)d_in[0];
    const float* df  = (const float*)d_in[1];
    const float* d2f = (const float*)d_in[2];
    float* out = (float*)d_out;

    const int P1_SMEM = 2 * 128 * 128 * 4;   // 131072 B
    const int P2_SMEM = 4 * 4224 * 4;        // 67584 B

    cudaFuncSetAttribute(p1_kernel, cudaFuncAttributeMaxDynamicSharedMemorySize, P1_SMEM);
    cudaFuncSetAttribute(p2_kernel, cudaFuncAttributeMaxDynamicSharedMemorySize, P2_SMEM);

    p1_kernel<<<SLICES, 512, P1_SMEM>>>(x);
    p2_kernel<<<dim3(SLICES, 4), 512, P2_SMEM>>>(out, df, d2f);
}